// round 12
// baseline (speedup 1.0000x reference)
#include <cuda_runtime.h>
#include <cuda_bf16.h>
#include <math.h>
#include <stdint.h>

#define NPTS 65536
#define Wdim 176
#define Ddim 132
#define LATD 128
#define OUTD 257
#define GB 8192

__device__ float g_bias[NPTS * LATD];
__device__ float g_partial[GB];
__device__ float g_scale;
__device__ int g_done;
__device__ uint32_t g_wh[81920];
__device__ uint32_t g_wl[81920];

// ---------------- helpers ----------------
__device__ __forceinline__ float sp100(float x) {
    return (x > 0.2f) ? x : (__logf(1.0f + __expf(x * 100.0f)) * 0.01f);
}
__device__ __forceinline__ uint32_t smem_u32(const void* p) {
    uint32_t a;
    asm("{ .reg .u64 t; cvta.to.shared.u64 t, %1; cvt.u32.u64 %0, t; }" : "=r"(a) : "l"(p));
    return a;
}
__device__ __forceinline__ uint32_t swz(int r, int cp) {  // cp = even col idx, 256B rows
    const int kc = cp >> 3;
    return (uint32_t)(r * 256 + (((kc ^ (r & 7)) << 4) | ((cp * 2) & 15)));
}
__device__ __forceinline__ void split2(float a, float b, uint32_t& hi, uint32_t& lo) {
    __nv_bfloat16 ah = __float2bfloat16_rn(a), bh = __float2bfloat16_rn(b);
    __nv_bfloat16 al = __float2bfloat16_rn(a - __bfloat162float(ah));
    __nv_bfloat16 bl = __float2bfloat16_rn(b - __bfloat162float(bh));
    hi = (uint32_t)__bfloat16_as_ushort(ah) | ((uint32_t)__bfloat16_as_ushort(bh) << 16);
    lo = (uint32_t)__bfloat16_as_ushort(al) | ((uint32_t)__bfloat16_as_ushort(bl) << 16);
}
// reconstruct the two fp32 values from paired hi/lo bf16x2 regs
__device__ __forceinline__ float2 upk(uint32_t h, uint32_t l) {
    float lo = __uint_as_float(h << 16) + __uint_as_float(l << 16);
    float hi = __uint_as_float(h & 0xFFFF0000u) + __uint_as_float(l & 0xFFFF0000u);
    return make_float2(lo, hi);
}
#define LDSM_X4(r, a) asm volatile( \
    "ldmatrix.sync.aligned.m8n8.x4.shared.b16 {%0,%1,%2,%3}, [%4];" \
    : "=r"((r)[0]), "=r"((r)[1]), "=r"((r)[2]), "=r"((r)[3]) : "r"(a))
#define MMA(c, a, b0, b1) asm volatile( \
    "mma.sync.aligned.m16n8k16.row.col.f32.bf16.bf16.f32 " \
    "{%0,%1,%2,%3}, {%4,%5,%6,%7}, {%8,%9}, {%0,%1,%2,%3};" \
    : "+f"((c)[0]), "+f"((c)[1]), "+f"((c)[2]), "+f"((c)[3]) \
    : "r"((a)[0]), "r"((a)[1]), "r"((a)[2]), "r"((a)[3]), "r"(b0), "r"(b1))
#define CPA(dst, src) asm volatile("cp.async.cg.shared.global [%0], [%1], 16;" \
    :: "r"(dst), "l"(src) : "memory")
#define CPA_COMMIT() asm volatile("cp.async.commit_group;" ::: "memory")
#define CPA_WAIT1() asm volatile("cp.async.wait_group 1;" ::: "memory")
#define CPA_WAIT0() asm volatile("cp.async.wait_group 0;" ::: "memory")

// ============ k_prep: split+swizzle weights [8 mid | lastA | lastB] ============
struct PW { const float* mid[8]; const float* last; };

__global__ void __launch_bounds__(256) k_prep(PW wp) {
    const int id = blockIdx.x * 256 + threadIdx.x;   // 81920 total
    if (id == 0) g_done = 0;
    const float* src;
    int r, cp, nvalid, obase;
    if (id < 65536) {
        const int l = id >> 13, rem = id & 8191;
        r = rem >> 6; cp = (rem & 63) * 2;
        nvalid = (l == 3) ? 125 : 128;
        src = wp.mid[l];
        obase = l * 8192;
    } else if (id < 73728) {
        const int rem = id - 65536;
        r = rem >> 6; cp = (rem & 63) * 2;
        nvalid = 128; src = wp.last; obase = 65536;   // W9 rows 0..127
    } else {
        const int rem = id - 73728;
        r = rem >> 6; cp = (rem & 63) * 2;
        nvalid = 128; src = wp.last + 128 * 128; obase = 73728;  // W9 rows 128..255
    }
    float2 wv = make_float2(0.f, 0.f);
    if (r < nvalid) wv = *(const float2*)(src + (size_t)r * 128 + cp);
    uint32_t hi, lo;
    split2(wv.x, wv.y, hi, lo);
    const uint32_t o = obase + (swz(r, cp) >> 2);
    g_wh[o] = hi; g_wl[o] = lo;
}

__global__ void k_nop() {}

// ============ k_gather: frozen (volume mix + Wq proj + fused reduce) ============
__global__ void __launch_bounds__(256) k_gather(
    const float* __restrict__ pixel, const float* __restrict__ vol,
    const float* __restrict__ Wq, const float* __restrict__ bq)
{
    __shared__ float sWqT[32 * 129];
    __shared__ float sred[8];
    __shared__ bool slast;
    const int tid = threadIdx.x;
    for (int i = tid; i < 4096; i += 256) sWqT[(i & 31) * 129 + (i >> 5)] = Wq[i];
    __syncthreads();

    const int warp_g = (blockIdx.x * 256 + tid) >> 5;
    const int lane = tid & 31;
    const float qx = pixel[warp_g * 3 + 0] + 24.0f;
    const float qy = pixel[warp_g * 3 + 1] + 24.0f;
    const float qz = ((pixel[warp_g * 3 + 2] - 425.0f) / 480.0f) * 128.0f;
    const int bx = (int)floorf(qx), by = (int)floorf(qy), bz = (int)floorf(qz);

    float acc = 0.0f;
#pragma unroll 8
    for (int k = 0; k < 64; k++) {
        const int ix = bx + (k >> 4) - 1;
        const int iy = by + ((k >> 2) & 3) - 1;
        const int iz = bz + (k & 3) - 1;
        const float sim = (float)ix * qx + (float)iy * qy + (float)iz * qz;
        acc += sim * __ldg(vol + (((ix * Wdim) + iy) * Ddim + iz) * 32 + lane);
    }
    float tot = acc;
#pragma unroll
    for (int o = 16; o; o >>= 1) tot += __shfl_xor_sync(0xffffffffu, tot, o);
    const float feat = acc / tot;

    float r0 = bq[lane], r1 = bq[lane + 32], r2 = bq[lane + 64], r3 = bq[lane + 96];
#pragma unroll 8
    for (int f = 0; f < 32; f++) {
        const float xf = __shfl_sync(0xffffffffu, feat, f);
        const float* wr = sWqT + f * 129 + lane;
        r0 += wr[0] * xf; r1 += wr[32] * xf; r2 += wr[64] * xf; r3 += wr[96] * xf;
    }
    float* bp = g_bias + (size_t)warp_g * LATD;
    bp[lane] = r0; bp[lane + 32] = r1; bp[lane + 64] = r2; bp[lane + 96] = r3;

    float s = fabsf(r0) + fabsf(r1) + fabsf(r2) + fabsf(r3);
#pragma unroll
    for (int o = 16; o; o >>= 1) s += __shfl_xor_sync(0xffffffffu, s, o);
    if (lane == 0) sred[tid >> 5] = s;
    __syncthreads();
    if (tid == 0) {
        float t = 0.0f;
        for (int i = 0; i < 8; i++) t += sred[i];
        g_partial[blockIdx.x] = t;
        __threadfence();
        slast = (atomicAdd(&g_done, 1) == GB - 1);
    }
    __syncthreads();
    if (slast) {
        float t = 0.0f;
        for (int i = tid; i < GB; i += 256) t += g_partial[i];
        __shared__ float sm2[256];
        sm2[tid] = t;
        __syncthreads();
        for (int o = 128; o; o >>= 1) {
            if (tid < o) sm2[tid] += sm2[tid + o];
            __syncthreads();
        }
        if (tid == 0) g_scale = ((float)NPTS * (float)LATD) / sm2[0];
    }
}

// ============ fused MLP: activations live in registers across layers ============
// smem = W double buffer only: buf(s) at (s&1)*65536, {H 32K | L 32K}
#define SMEM_FUSED 131072

struct FParams {
    const float* world;
    const float* W0;
    const float* W9;
    const float* b[10];
    float* out;
};

__device__ __forceinline__ void prefetch_w(uint32_t sb, int s, int tid) {
    const uint32_t dh = sb + (uint32_t)((s & 1) * 65536);
    const uint32_t dl = dh + 32768u;
    const int off = (s <= 8) ? (s - 1) * 8192 : ((s == 9) ? 65536 : 73728);
    const uint8_t* gh = (const uint8_t*)(g_wh + off);
    const uint8_t* gl = (const uint8_t*)(g_wl + off);
#pragma unroll
    for (int i = tid * 16; i < 32768; i += 256 * 16) {
        CPA(dh + i, gh + i);
        CPA(dl + i, gl + i);
    }
}

// one layer's MMAs: warp tile 16m x 128n; A from registers, B from smem
__device__ __forceinline__ void mma_phase(
    uint32_t wbh, uint32_t wbl, int T,
    const uint32_t* ahi, const uint32_t* alo, float (*acc)[4])
{
    const int t7 = T & 7;
    const int khalf = (T >> 3) & 1;
    const int nsel8 = ((T >> 4) & 1) * 8;
#pragma unroll
    for (int ks = 0; ks < 8; ks++) {
        const uint32_t kx = (uint32_t)(((2 * ks + khalf) ^ t7) << 4);
        const uint32_t rowb = (uint32_t)((nsel8 + t7) * 256) + kx;
#pragma unroll
        for (int nb = 0; nb < 16; nb += 2) {
            uint32_t bh[4], bl4[4];
            const uint32_t bo = rowb + (uint32_t)(nb * 2048);
            LDSM_X4(bh, wbh + bo);
            LDSM_X4(bl4, wbl + bo);
            MMA(acc[nb],     ahi + 4 * ks, bh[0],  bh[1]);
            MMA(acc[nb + 1], ahi + 4 * ks, bh[2],  bh[3]);
            MMA(acc[nb],     ahi + 4 * ks, bl4[0], bl4[1]);
            MMA(acc[nb + 1], ahi + 4 * ks, bl4[2], bl4[3]);
            MMA(acc[nb],     alo + 4 * ks, bh[0],  bh[1]);
            MMA(acc[nb + 1], alo + 4 * ks, bh[2],  bh[3]);
        }
    }
}

__global__ void __launch_bounds__(256, 1) k_fused(FParams p) {
    extern __shared__ uint8_t sm[];
    const int tid = threadIdx.x, w = tid >> 5, T = tid & 31;
    const int m0 = blockIdx.x * 128;
    const uint32_t sb = smem_u32(sm);
    const int mb = w * 16;
    const int c0 = (T & 3) * 2;
    const int rg1 = m0 + mb + (T >> 2), rg2 = rg1 + 8;

    prefetch_w(sb, 1, tid);
    CPA_COMMIT();

    uint32_t ahi[32], alo[32];
    float acc[16][4];

    // ---- layer 0 (3->128) * bias * scale -> softplus -> A fragments ----
    {
        const float sc = g_scale;
        const float* b0 = p.b[0];
        const float w1x = p.world[(size_t)rg1 * 3], w1y = p.world[(size_t)rg1 * 3 + 1],
                    w1z = p.world[(size_t)rg1 * 3 + 2];
        const float w2x = p.world[(size_t)rg2 * 3], w2y = p.world[(size_t)rg2 * 3 + 1],
                    w2z = p.world[(size_t)rg2 * 3 + 2];
#pragma unroll
        for (int nb = 0; nb < 16; nb++) {
            const int c = nb * 8 + c0;
            const float wa0 = p.W0[c * 3], wa1 = p.W0[c * 3 + 1], wa2 = p.W0[c * 3 + 2];
            const float wb0 = p.W0[c * 3 + 3], wb1 = p.W0[c * 3 + 4], wb2 = p.W0[c * 3 + 5];
            float y0 = b0[c]     + wa0 * w1x + wa1 * w1y + wa2 * w1z;
            float y1 = b0[c + 1] + wb0 * w1x + wb1 * w1y + wb2 * w1z;
            float y2 = b0[c]     + wa0 * w2x + wa1 * w2y + wa2 * w2z;
            float y3 = b0[c + 1] + wb0 * w2x + wb1 * w2y + wb2 * w2z;
            y0 *= g_bias[(size_t)rg1 * LATD + c] * sc;
            y1 *= g_bias[(size_t)rg1 * LATD + c + 1] * sc;
            y2 *= g_bias[(size_t)rg2 * LATD + c] * sc;
            y3 *= g_bias[(size_t)rg2 * LATD + c + 1] * sc;
            const int i0 = (nb >> 1) * 4 + (nb & 1) * 2;
            split2(sp100(y0), sp100(y1), ahi[i0], alo[i0]);
            split2(sp100(y2), sp100(y3), ahi[i0 + 1], alo[i0 + 1]);
        }
    }

    for (int s = 1; s <= 10; s++) {
        __syncthreads();   // all warps finished MMA(s-1): safe to overwrite buf (s+1)&1
        if (s < 10) { prefetch_w(sb, s + 1, tid); CPA_COMMIT(); CPA_WAIT1(); }
        else CPA_WAIT0();
        __syncthreads();   // prefetch(s) data visible to all warps
        const uint32_t wbh = sb + (uint32_t)((s & 1) * 65536);
        const uint32_t wbl = wbh + 32768u;

#pragma unroll
        for (int i = 0; i < 16; i++)
#pragma unroll
            for (int j = 0; j < 4; j++) acc[i][j] = 0.f;
        mma_phase(wbh, wbl, T, ahi, alo, acc);

        if (s <= 8) {
            const float* bs = p.b[s];
            const bool skl = (s == 4);
            float wv1x = 0.f, wv1y = 0.f, wv1z = 0.f, wv2x = 0.f, wv2y = 0.f, wv2z = 0.f;
            if (skl) {
                wv1x = p.world[(size_t)rg1 * 3]; wv1y = p.world[(size_t)rg1 * 3 + 1];
                wv1z = p.world[(size_t)rg1 * 3 + 2];
                wv2x = p.world[(size_t)rg2 * 3]; wv2y = p.world[(size_t)rg2 * 3 + 1];
                wv2z = p.world[(size_t)rg2 * 3 + 2];
            }
#pragma unroll
            for (int nb = 0; nb < 16; nb++) {
                const int c = nb * 8 + c0;
                const float bv0 = bs[c], bv1 = bs[c + 1];
                float y0 = acc[nb][0] + bv0, y1 = acc[nb][1] + bv1;
                float y2 = acc[nb][2] + bv0, y3 = acc[nb][3] + bv1;
                if (skl && c >= 125) {
                    y0 = (c == 125) ? wv1x : ((c == 126) ? wv1y : wv1z);
                    y2 = (c == 125) ? wv2x : ((c == 126) ? wv2y : wv2z);
                }
                if (skl && c + 1 >= 125) {
                    y1 = (c + 1 == 125) ? wv1x : ((c + 1 == 126) ? wv1y : wv1z);
                    y3 = (c + 1 == 125) ? wv2x : ((c + 1 == 126) ? wv2y : wv2z);
                }
                const int i0 = (nb >> 1) * 4 + (nb & 1) * 2;
                split2(sp100(y0), sp100(y1), ahi[i0], alo[i0]);
                split2(sp100(y2), sp100(y3), ahi[i0 + 1], alo[i0 + 1]);
            }
        } else {
            const float* b9 = p.b[9];
            const int base = (s == 9) ? 0 : 128;
            float* o1 = p.out + (size_t)rg1 * OUTD + base;
            float* o2 = p.out + (size_t)rg2 * OUTD + base;
#pragma unroll
            for (int nb = 0; nb < 16; nb++) {
                const int c = nb * 8 + c0;
                o1[c]     = acc[nb][0] + b9[base + c];
                o1[c + 1] = acc[nb][1] + b9[base + c + 1];
                o2[c]     = acc[nb][2] + b9[base + c];
                o2[c + 1] = acc[nb][3] + b9[base + c + 1];
            }
            if (s == 10) {
                // col 256: dot(X_row, W9[256,:]) via register A frags + shfl reduce
                const float* w9c = p.W9 + 256 * 128;
                float s1 = 0.f, s2 = 0.f;
#pragma unroll
                for (int ks = 0; ks < 8; ks++) {
                    const int k0 = ks * 16 + c0;
                    const float wk0 = w9c[k0], wk1 = w9c[k0 + 1];
                    const float wk8 = w9c[k0 + 8], wk9 = w9c[k0 + 9];
                    float2 xa = upk(ahi[4 * ks],     alo[4 * ks]);
                    float2 xb = upk(ahi[4 * ks + 1], alo[4 * ks + 1]);
                    float2 xc = upk(ahi[4 * ks + 2], alo[4 * ks + 2]);
                    float2 xd = upk(ahi[4 * ks + 3], alo[4 * ks + 3]);
                    s1 += xa.x * wk0 + xa.y * wk1 + xc.x * wk8 + xc.y * wk9;
                    s2 += xb.x * wk0 + xb.y * wk1 + xd.x * wk8 + xd.y * wk9;
                }
                s1 += __shfl_xor_sync(0xffffffffu, s1, 1);
                s1 += __shfl_xor_sync(0xffffffffu, s1, 2);
                s2 += __shfl_xor_sync(0xffffffffu, s2, 1);
                s2 += __shfl_xor_sync(0xffffffffu, s2, 2);
                if ((T & 3) == 0) {
                    p.out[(size_t)rg1 * OUTD + 256] = s1 + b9[256];
                    p.out[(size_t)rg2 * OUTD + 256] = s2 + b9[256];
                }
            }
        }
    }
}

// ======================================================================
extern "C" void kernel_launch(void* const* d_in, const int* in_sizes, int n_in,
                              void* d_out, int out_size)
{
    const float* world = (const float*)d_in[0];
    const float* pixel = (const float*)d_in[1];
    const float* vol   = (const float*)d_in[2];
    const float* Wq    = (const float*)d_in[3];
    const float* bq    = (const float*)d_in[4];
    const float* Wl[10];
    const float* bl[10];
    for (int l = 0; l < 10; l++) {
        Wl[l] = (const float*)d_in[5 + 2 * l];
        bl[l] = (const float*)d_in[6 + 2 * l];
    }

    cudaFuncSetAttribute(k_fused, cudaFuncAttributeMaxDynamicSharedMemorySize, SMEM_FUSED);

    PW wp;
    for (int l = 0; l < 8; l++) wp.mid[l] = Wl[l + 1];
    wp.last = Wl[9];
    k_prep<<<320, 256>>>(wp);                    // idx 0

    k_gather<<<GB, 256>>>(pixel, vol, Wq, bq);   // idx 1

    k_nop<<<1, 32>>>();                          // idx 2

    FParams fp;
    fp.world = world;
    fp.W0 = Wl[0];
    fp.W9 = Wl[9];
    for (int l = 0; l < 10; l++) fp.b[l] = bl[l];
    fp.out = (float*)d_out;
    k_fused<<<NPTS / 128, 256, SMEM_FUSED>>>(fp);   // idx 3 <- ncu capture

    k_nop<<<1, 32>>>();                          // idx 4
}

// round 16
// speedup vs baseline: 1.0171x; 1.0171x over previous
#include <cuda_runtime.h>
#include <cuda_bf16.h>
#include <cuda_fp16.h>
#include <math.h>
#include <stdint.h>

#define NPTS 65536
#define Wdim 176
#define Ddim 132
#define LATD 128
#define OUTD 257
#define GB 8192

__device__ float g_bias[NPTS * LATD];
__device__ float g_partial[GB];
__device__ float g_scale;
__device__ int g_done;
__device__ uint32_t g_wh[81920];
__device__ uint32_t g_wl[81920];

// ---------------- helpers ----------------
__device__ __forceinline__ float sp100(float x) {
    return (x > 0.2f) ? x : (__logf(1.0f + __expf(x * 100.0f)) * 0.01f);
}
__device__ __forceinline__ uint32_t smem_u32(const void* p) {
    uint32_t a;
    asm("{ .reg .u64 t; cvta.to.shared.u64 t, %1; cvt.u32.u64 %0, t; }" : "=r"(a) : "l"(p));
    return a;
}
__device__ __forceinline__ uint32_t swz(int r, int cp) {  // cp = even col idx, 256B rows
    const int kc = cp >> 3;
    return (uint32_t)(r * 256 + (((kc ^ (r & 7)) << 4) | ((cp * 2) & 15)));
}
// fp16 hi/lo split of two floats, packed as f16x2 regs
__device__ __forceinline__ void splith(float a, float b, uint32_t& hi, uint32_t& lo) {
    __half ah = __float2half_rn(a), bh = __float2half_rn(b);
    __half al = __float2half_rn(a - __half2float(ah));
    __half bl = __float2half_rn(b - __half2float(bh));
    asm("mov.b32 %0, {%1, %2};" : "=r"(hi) : "h"(__half_as_ushort(ah)), "h"(__half_as_ushort(bh)));
    asm("mov.b32 %0, {%1, %2};" : "=r"(lo) : "h"(__half_as_ushort(al)), "h"(__half_as_ushort(bl)));
}
__device__ __forceinline__ float2 upkh(uint32_t h, uint32_t l) {
    __half2 hh = *reinterpret_cast<__half2*>(&h);
    __half2 ll = *reinterpret_cast<__half2*>(&l);
    return make_float2(__low2float(hh) + __low2float(ll), __high2float(hh) + __high2float(ll));
}
#define LDSM_X4(r, a) asm volatile( \
    "ldmatrix.sync.aligned.m8n8.x4.shared.b16 {%0,%1,%2,%3}, [%4];" \
    : "=r"((r)[0]), "=r"((r)[1]), "=r"((r)[2]), "=r"((r)[3]) : "r"(a))
#define MMAF(c, a, b0, b1) asm volatile( \
    "mma.sync.aligned.m16n8k16.row.col.f32.f16.f16.f32 " \
    "{%0,%1,%2,%3}, {%4,%5,%6,%7}, {%8,%9}, {%0,%1,%2,%3};" \
    : "+f"((c)[0]), "+f"((c)[1]), "+f"((c)[2]), "+f"((c)[3]) \
    : "r"((a)[0]), "r"((a)[1]), "r"((a)[2]), "r"((a)[3]), "r"(b0), "r"(b1))
#define MMAH(c, a, b0, b1) asm volatile( \
    "mma.sync.aligned.m16n8k16.row.col.f16.f16.f16.f16 " \
    "{%0,%1}, {%2,%3,%4,%5}, {%6,%7}, {%0,%1};" \
    : "+r"((c)[0]), "+r"((c)[1]) \
    : "r"((a)[0]), "r"((a)[1]), "r"((a)[2]), "r"((a)[3]), "r"(b0), "r"(b1))
#define CPA(dst, src) asm volatile("cp.async.cg.shared.global [%0], [%1], 16;" \
    :: "r"(dst), "l"(src) : "memory")
#define CPA_COMMIT() asm volatile("cp.async.commit_group;" ::: "memory")
#define CPA_WAIT1() asm volatile("cp.async.wait_group 1;" ::: "memory")
#define CPA_WAIT0() asm volatile("cp.async.wait_group 0;" ::: "memory")

// ============ k_prep: fp16 split+swizzle weights [8 mid | lastA | lastB] ============
struct PW { const float* mid[8]; const float* last; };

__global__ void __launch_bounds__(256) k_prep(PW wp) {
    const int id = blockIdx.x * 256 + threadIdx.x;   // 81920 total
    if (id == 0) g_done = 0;
    const float* src;
    int r, cp, nvalid, obase;
    if (id < 65536) {
        const int l = id >> 13, rem = id & 8191;
        r = rem >> 6; cp = (rem & 63) * 2;
        nvalid = (l == 3) ? 125 : 128;
        src = wp.mid[l];
        obase = l * 8192;
    } else if (id < 73728) {
        const int rem = id - 65536;
        r = rem >> 6; cp = (rem & 63) * 2;
        nvalid = 128; src = wp.last; obase = 65536;
    } else {
        const int rem = id - 73728;
        r = rem >> 6; cp = (rem & 63) * 2;
        nvalid = 128; src = wp.last + 128 * 128; obase = 73728;
    }
    float2 wv = make_float2(0.f, 0.f);
    if (r < nvalid) wv = *(const float2*)(src + (size_t)r * 128 + cp);
    uint32_t hi, lo;
    splith(wv.x, wv.y, hi, lo);
    const uint32_t o = obase + (swz(r, cp) >> 2);
    g_wh[o] = hi; g_wl[o] = lo;
}

__global__ void k_nop() {}

// ============ k_gather: frozen ============
__global__ void __launch_bounds__(256) k_gather(
    const float* __restrict__ pixel, const float* __restrict__ vol,
    const float* __restrict__ Wq, const float* __restrict__ bq)
{
    __shared__ float sWqT[32 * 129];
    __shared__ float sred[8];
    __shared__ bool slast;
    const int tid = threadIdx.x;
    for (int i = tid; i < 4096; i += 256) sWqT[(i & 31) * 129 + (i >> 5)] = Wq[i];
    __syncthreads();

    const int warp_g = (blockIdx.x * 256 + tid) >> 5;
    const int lane = tid & 31;
    const float qx = pixel[warp_g * 3 + 0] + 24.0f;
    const float qy = pixel[warp_g * 3 + 1] + 24.0f;
    const float qz = ((pixel[warp_g * 3 + 2] - 425.0f) / 480.0f) * 128.0f;
    const int bx = (int)floorf(qx), by = (int)floorf(qy), bz = (int)floorf(qz);

    float acc = 0.0f;
#pragma unroll 8
    for (int k = 0; k < 64; k++) {
        const int ix = bx + (k >> 4) - 1;
        const int iy = by + ((k >> 2) & 3) - 1;
        const int iz = bz + (k & 3) - 1;
        const float sim = (float)ix * qx + (float)iy * qy + (float)iz * qz;
        acc += sim * __ldg(vol + (((ix * Wdim) + iy) * Ddim + iz) * 32 + lane);
    }
    float tot = acc;
#pragma unroll
    for (int o = 16; o; o >>= 1) tot += __shfl_xor_sync(0xffffffffu, tot, o);
    const float feat = acc / tot;

    float r0 = bq[lane], r1 = bq[lane + 32], r2 = bq[lane + 64], r3 = bq[lane + 96];
#pragma unroll 8
    for (int f = 0; f < 32; f++) {
        const float xf = __shfl_sync(0xffffffffu, feat, f);
        const float* wr = sWqT + f * 129 + lane;
        r0 += wr[0] * xf; r1 += wr[32] * xf; r2 += wr[64] * xf; r3 += wr[96] * xf;
    }
    float* bp = g_bias + (size_t)warp_g * LATD;
    bp[lane] = r0; bp[lane + 32] = r1; bp[lane + 64] = r2; bp[lane + 96] = r3;

    float s = fabsf(r0) + fabsf(r1) + fabsf(r2) + fabsf(r3);
#pragma unroll
    for (int o = 16; o; o >>= 1) s += __shfl_xor_sync(0xffffffffu, s, o);
    if (lane == 0) sred[tid >> 5] = s;
    __syncthreads();
    if (tid == 0) {
        float t = 0.0f;
        for (int i = 0; i < 8; i++) t += sred[i];
        g_partial[blockIdx.x] = t;
        __threadfence();
        slast = (atomicAdd(&g_done, 1) == GB - 1);
    }
    __syncthreads();
    if (slast) {
        float t = 0.0f;
        for (int i = tid; i < GB; i += 256) t += g_partial[i];
        __shared__ float sm2[256];
        sm2[tid] = t;
        __syncthreads();
        for (int o = 128; o; o >>= 1) {
            if (tid < o) sm2[tid] += sm2[tid + o];
            __syncthreads();
        }
        if (tid == 0) g_scale = ((float)NPTS * (float)LATD) / sm2[0];
    }
}

// ============ fused MLP: register A, f32-acc main + f16-acc corrections ============
#define SMEM_FUSED 131072

struct FParams {
    const float* world;
    const float* W0;
    const float* W9;
    const float* b[10];
    float* out;
};

__device__ __forceinline__ void prefetch_w(uint32_t sb, int s, int tid) {
    const uint32_t dh = sb + (uint32_t)((s & 1) * 65536);
    const uint32_t dl = dh + 32768u;
    const int off = (s <= 8) ? (s - 1) * 8192 : ((s == 9) ? 65536 : 73728);
    const uint8_t* gh = (const uint8_t*)(g_wh + off);
    const uint8_t* gl = (const uint8_t*)(g_wl + off);
#pragma unroll
    for (int i = tid * 16; i < 32768; i += 256 * 16) {
        CPA(dh + i, gh + i);
        CPA(dl + i, gl + i);
    }
}

__device__ __forceinline__ void mma_phase(
    uint32_t wbh, uint32_t wbl, int T,
    const uint32_t* ahi, const uint32_t* alo,
    float (*accm)[4], uint32_t (*accc)[2])
{
    const int t7 = T & 7;
    const int khalf = (T >> 3) & 1;
    const int nsel8 = ((T >> 4) & 1) * 8;
#pragma unroll
    for (int ks = 0; ks < 8; ks++) {
        const uint32_t kx = (uint32_t)(((2 * ks + khalf) ^ t7) << 4);
        const uint32_t rowb = (uint32_t)((nsel8 + t7) * 256) + kx;
#pragma unroll
        for (int nb = 0; nb < 16; nb += 2) {
            uint32_t bh[4], bl4[4];
            const uint32_t bo = rowb + (uint32_t)(nb * 2048);
            LDSM_X4(bh, wbh + bo);
            LDSM_X4(bl4, wbl + bo);
            MMAF(accm[nb],     ahi + 4 * ks, bh[0],  bh[1]);
            MMAF(accm[nb + 1], ahi + 4 * ks, bh[2],  bh[3]);
            MMAH(accc[nb],     ahi + 4 * ks, bl4[0], bl4[1]);
            MMAH(accc[nb + 1], ahi + 4 * ks, bl4[2], bl4[3]);
            MMAH(accc[nb],     alo + 4 * ks, bh[0],  bh[1]);
            MMAH(accc[nb + 1], alo + 4 * ks, bh[2],  bh[3]);
        }
    }
}

__global__ void __launch_bounds__(256) k_fused(FParams p) {
    extern __shared__ uint8_t sm[];
    const int tid = threadIdx.x, w = tid >> 5, T = tid & 31;
    const int m0 = blockIdx.x * 128;
    const uint32_t sb = smem_u32(sm);
    const int mb = w * 16;
    const int c0 = (T & 3) * 2;
    const int rg1 = m0 + mb + (T >> 2), rg2 = rg1 + 8;

    prefetch_w(sb, 1, tid);
    CPA_COMMIT();

    uint32_t ahi[32], alo[32];
    float accm[16][4];
    uint32_t accc[16][2];

    // ---- layer 0 (3->128) * bias * scale -> softplus -> A fragments ----
    {
        const float sc = g_scale;
        const float* b0 = p.b[0];
        const float w1x = p.world[(size_t)rg1 * 3], w1y = p.world[(size_t)rg1 * 3 + 1],
                    w1z = p.world[(size_t)rg1 * 3 + 2];
        const float w2x = p.world[(size_t)rg2 * 3], w2y = p.world[(size_t)rg2 * 3 + 1],
                    w2z = p.world[(size_t)rg2 * 3 + 2];
#pragma unroll
        for (int nb = 0; nb < 16; nb++) {
            const int c = nb * 8 + c0;
            const float wa0 = p.W0[c * 3], wa1 = p.W0[c * 3 + 1], wa2 = p.W0[c * 3 + 2];
            const float wb0 = p.W0[c * 3 + 3], wb1 = p.W0[c * 3 + 4], wb2 = p.W0[c * 3 + 5];
            float y0 = b0[c]     + wa0 * w1x + wa1 * w1y + wa2 * w1z;
            float y1 = b0[c + 1] + wb0 * w1x + wb1 * w1y + wb2 * w1z;
            float y2 = b0[c]     + wa0 * w2x + wa1 * w2y + wa2 * w2z;
            float y3 = b0[c + 1] + wb0 * w2x + wb1 * w2y + wb2 * w2z;
            y0 *= g_bias[(size_t)rg1 * LATD + c] * sc;
            y1 *= g_bias[(size_t)rg1 * LATD + c + 1] * sc;
            y2 *= g_bias[(size_t)rg2 * LATD + c] * sc;
            y3 *= g_bias[(size_t)rg2 * LATD + c + 1] * sc;
            const int i0 = (nb >> 1) * 4 + (nb & 1) * 2;
            splith(sp100(y0), sp100(y1), ahi[i0], alo[i0]);
            splith(sp100(y2), sp100(y3), ahi[i0 + 1], alo[i0 + 1]);
        }
    }

    for (int s = 1; s <= 10; s++) {
        __syncthreads();
        if (s < 10) { prefetch_w(sb, s + 1, tid); CPA_COMMIT(); CPA_WAIT1(); }
        else CPA_WAIT0();
        __syncthreads();
        const uint32_t wbh = sb + (uint32_t)((s & 1) * 65536);
        const uint32_t wbl = wbh + 32768u;

#pragma unroll
        for (int i = 0; i < 16; i++) {
#pragma unroll
            for (int j = 0; j < 4; j++) accm[i][j] = 0.f;
            accc[i][0] = 0u; accc[i][1] = 0u;
        }
        mma_phase(wbh, wbl, T, ahi, alo, accm, accc);

        if (s <= 8) {
            const float* bs = p.b[s];
            const bool skl = (s == 4);
            float wv1x = 0.f, wv1y = 0.f, wv1z = 0.f, wv2x = 0.f, wv2y = 0.f, wv2z = 0.f;
            if (skl) {
                wv1x = p.world[(size_t)rg1 * 3]; wv1y = p.world[(size_t)rg1 * 3 + 1];
                wv1z = p.world[(size_t)rg1 * 3 + 2];
                wv2x = p.world[(size_t)rg2 * 3]; wv2y = p.world[(size_t)rg2 * 3 + 1];
                wv2z = p.world[(size_t)rg2 * 3 + 2];
            }
#pragma unroll
            for (int nb = 0; nb < 16; nb++) {
                const int c = nb * 8 + c0;
                const float bv0 = bs[c], bv1 = bs[c + 1];
                const __half2 h1 = *reinterpret_cast<__half2*>(&accc[nb][0]);
                const __half2 h2 = *reinterpret_cast<__half2*>(&accc[nb][1]);
                float y0 = accm[nb][0] + __low2float(h1) + bv0;
                float y1 = accm[nb][1] + __high2float(h1) + bv1;
                float y2 = accm[nb][2] + __low2float(h2) + bv0;
                float y3 = accm[nb][3] + __high2float(h2) + bv1;
                if (skl && c >= 125) {
                    y0 = (c == 125) ? wv1x : ((c == 126) ? wv1y : wv1z);
                    y2 = (c == 125) ? wv2x : ((c == 126) ? wv2y : wv2z);
                }
                if (skl && c + 1 >= 125) {
                    y1 = (c + 1 == 125) ? wv1x : ((c + 1 == 126) ? wv1y : wv1z);
                    y3 = (c + 1 == 125) ? wv2x : ((c + 1 == 126) ? wv2y : wv2z);
                }
                const int i0 = (nb >> 1) * 4 + (nb & 1) * 2;
                splith(sp100(y0), sp100(y1), ahi[i0], alo[i0]);
                splith(sp100(y2), sp100(y3), ahi[i0 + 1], alo[i0 + 1]);
            }
        } else {
            const float* b9 = p.b[9];
            const int base = (s == 9) ? 0 : 128;
            float* o1 = p.out + (size_t)rg1 * OUTD + base;
            float* o2 = p.out + (size_t)rg2 * OUTD + base;
#pragma unroll
            for (int nb = 0; nb < 16; nb++) {
                const int c = nb * 8 + c0;
                const __half2 h1 = *reinterpret_cast<__half2*>(&accc[nb][0]);
                const __half2 h2 = *reinterpret_cast<__half2*>(&accc[nb][1]);
                o1[c]     = accm[nb][0] + __low2float(h1) + b9[base + c];
                o1[c + 1] = accm[nb][1] + __high2float(h1) + b9[base + c + 1];
                o2[c]     = accm[nb][2] + __low2float(h2) + b9[base + c];
                o2[c + 1] = accm[nb][3] + __high2float(h2) + b9[base + c + 1];
            }
            if (s == 10) {
                const float* w9c = p.W9 + 256 * 128;
                float s1 = 0.f, s2 = 0.f;
#pragma unroll
                for (int ks = 0; ks < 8; ks++) {
                    const int k0 = ks * 16 + c0;
                    const float wk0 = w9c[k0], wk1 = w9c[k0 + 1];
                    const float wk8 = w9c[k0 + 8], wk9 = w9c[k0 + 9];
                    float2 xa = upkh(ahi[4 * ks],     alo[4 * ks]);
                    float2 xb = upkh(ahi[4 * ks + 1], alo[4 * ks + 1]);
                    float2 xc = upkh(ahi[4 * ks + 2], alo[4 * ks + 2]);
                    float2 xd = upkh(ahi[4 * ks + 3], alo[4 * ks + 3]);
                    s1 += xa.x * wk0 + xa.y * wk1 + xc.x * wk8 + xc.y * wk9;
                    s2 += xb.x * wk0 + xb.y * wk1 + xd.x * wk8 + xd.y * wk9;
                }
                s1 += __shfl_xor_sync(0xffffffffu, s1, 1);
                s1 += __shfl_xor_sync(0xffffffffu, s1, 2);
                s2 += __shfl_xor_sync(0xffffffffu, s2, 1);
                s2 += __shfl_xor_sync(0xffffffffu, s2, 2);
                if ((T & 3) == 0) {
                    p.out[(size_t)rg1 * OUTD + 256] = s1 + b9[256];
                    p.out[(size_t)rg2 * OUTD + 256] = s2 + b9[256];
                }
            }
        }
    }
}

// ======================================================================
extern "C" void kernel_launch(void* const* d_in, const int* in_sizes, int n_in,
                              void* d_out, int out_size)
{
    const float* world = (const float*)d_in[0];
    const float* pixel = (const float*)d_in[1];
    const float* vol   = (const float*)d_in[2];
    const float* Wq    = (const float*)d_in[3];
    const float* bq    = (const float*)d_in[4];
    const float* Wl[10];
    const float* bl[10];
    for (int l = 0; l < 10; l++) {
        Wl[l] = (const float*)d_in[5 + 2 * l];
        bl[l] = (const float*)d_in[6 + 2 * l];
    }

    cudaFuncSetAttribute(k_fused, cudaFuncAttributeMaxDynamicSharedMemorySize, SMEM_FUSED);

    PW wp;
    for (int l = 0; l < 8; l++) wp.mid[l] = Wl[l + 1];
    wp.last = Wl[9];
    k_prep<<<320, 256>>>(wp);                    // idx 0

    k_gather<<<GB, 256>>>(pixel, vol, Wq, bq);   // idx 1

    k_nop<<<1, 32>>>();                          // idx 2

    FParams fp;
    fp.world = world;
    fp.W0 = Wl[0];
    fp.W9 = Wl[9];
    for (int l = 0; l < 10; l++) fp.b[l] = bl[l];
    fp.out = (float*)d_out;
    k_fused<<<NPTS / 128, 256, SMEM_FUSED>>>(fp);   // idx 3 <- ncu capture

    k_nop<<<1, 32>>>();                          // idx 4
}

// round 17
// speedup vs baseline: 1.0945x; 1.0761x over previous
#include <cuda_runtime.h>
#include <cuda_bf16.h>
#include <cuda_fp16.h>
#include <math.h>
#include <stdint.h>

#define NPTS 65536
#define Wdim 176
#define Ddim 132
#define LATD 128
#define OUTD 257
#define GB 8192

__device__ float g_bias[NPTS * LATD];
__device__ float g_partial[GB];
__device__ float g_scale;
__device__ int g_done;
__device__ uint32_t g_wh[81920];
__device__ uint32_t g_wl[81920];

// ---------------- helpers ----------------
__device__ __forceinline__ float sp100(float x) {
    return (x > 0.2f) ? x : (__logf(1.0f + __expf(x * 100.0f)) * 0.01f);
}
__device__ __forceinline__ uint32_t smem_u32(const void* p) {
    uint32_t a;
    asm("{ .reg .u64 t; cvta.to.shared.u64 t, %1; cvt.u32.u64 %0, t; }" : "=r"(a) : "l"(p));
    return a;
}
__device__ __forceinline__ uint32_t swz(int r, int cp) {  // cp = even col idx, 256B rows
    const int kc = cp >> 3;
    return (uint32_t)(r * 256 + (((kc ^ (r & 7)) << 4) | ((cp * 2) & 15)));
}
__device__ __forceinline__ void splith(float a, float b, uint32_t& hi, uint32_t& lo) {
    __half ah = __float2half_rn(a), bh = __float2half_rn(b);
    __half al = __float2half_rn(a - __half2float(ah));
    __half bl = __float2half_rn(b - __half2float(bh));
    asm("mov.b32 %0, {%1, %2};" : "=r"(hi) : "h"(__half_as_ushort(ah)), "h"(__half_as_ushort(bh)));
    asm("mov.b32 %0, {%1, %2};" : "=r"(lo) : "h"(__half_as_ushort(al)), "h"(__half_as_ushort(bl)));
}
__device__ __forceinline__ float2 upkh(uint32_t h, uint32_t l) {
    __half2 hh = *reinterpret_cast<__half2*>(&h);
    __half2 ll = *reinterpret_cast<__half2*>(&l);
    return make_float2(__low2float(hh) + __low2float(ll), __high2float(hh) + __high2float(ll));
}
#define LDSM_X4(r, a) asm volatile( \
    "ldmatrix.sync.aligned.m8n8.x4.shared.b16 {%0,%1,%2,%3}, [%4];" \
    : "=r"((r)[0]), "=r"((r)[1]), "=r"((r)[2]), "=r"((r)[3]) : "r"(a))
#define MMAF(c, a, b0, b1) asm volatile( \
    "mma.sync.aligned.m16n8k16.row.col.f32.f16.f16.f32 " \
    "{%0,%1,%2,%3}, {%4,%5,%6,%7}, {%8,%9}, {%0,%1,%2,%3};" \
    : "+f"((c)[0]), "+f"((c)[1]), "+f"((c)[2]), "+f"((c)[3]) \
    : "r"((a)[0]), "r"((a)[1]), "r"((a)[2]), "r"((a)[3]), "r"(b0), "r"(b1))
#define MMAH(c, a, b0, b1) asm volatile( \
    "mma.sync.aligned.m16n8k16.row.col.f16.f16.f16.f16 " \
    "{%0,%1}, {%2,%3,%4,%5}, {%6,%7}, {%0,%1};" \
    : "+r"((c)[0]), "+r"((c)[1]) \
    : "r"((a)[0]), "r"((a)[1]), "r"((a)[2]), "r"((a)[3]), "r"(b0), "r"(b1))
#define CPA(dst, src) asm volatile("cp.async.cg.shared.global [%0], [%1], 16;" \
    :: "r"(dst), "l"(src) : "memory")
#define CPA_COMMIT() asm volatile("cp.async.commit_group;" ::: "memory")
#define CPA_WAIT0() asm volatile("cp.async.wait_group 0;" ::: "memory")

// ============ k_prep: fp16 split+swizzle weights [8 mid | lastA | lastB] ============
struct PW { const float* mid[8]; const float* last; };

__global__ void __launch_bounds__(256) k_prep(PW wp) {
    const int id = blockIdx.x * 256 + threadIdx.x;   // 81920 total
    if (id == 0) g_done = 0;
    const float* src;
    int r, cp, nvalid, obase;
    if (id < 65536) {
        const int l = id >> 13, rem = id & 8191;
        r = rem >> 6; cp = (rem & 63) * 2;
        nvalid = (l == 3) ? 125 : 128;
        src = wp.mid[l];
        obase = l * 8192;
    } else if (id < 73728) {
        const int rem = id - 65536;
        r = rem >> 6; cp = (rem & 63) * 2;
        nvalid = 128; src = wp.last; obase = 65536;
    } else {
        const int rem = id - 73728;
        r = rem >> 6; cp = (rem & 63) * 2;
        nvalid = 128; src = wp.last + 128 * 128; obase = 73728;
    }
    float2 wv = make_float2(0.f, 0.f);
    if (r < nvalid) wv = *(const float2*)(src + (size_t)r * 128 + cp);
    uint32_t hi, lo;
    splith(wv.x, wv.y, hi, lo);
    const uint32_t o = obase + (swz(r, cp) >> 2);
    g_wh[o] = hi; g_wl[o] = lo;
}

__global__ void k_nop() {}

// ============ k_gather: frozen ============
__global__ void __launch_bounds__(256) k_gather(
    const float* __restrict__ pixel, const float* __restrict__ vol,
    const float* __restrict__ Wq, const float* __restrict__ bq)
{
    __shared__ float sWqT[32 * 129];
    __shared__ float sred[8];
    __shared__ bool slast;
    const int tid = threadIdx.x;
    for (int i = tid; i < 4096; i += 256) sWqT[(i & 31) * 129 + (i >> 5)] = Wq[i];
    __syncthreads();

    const int warp_g = (blockIdx.x * 256 + tid) >> 5;
    const int lane = tid & 31;
    const float qx = pixel[warp_g * 3 + 0] + 24.0f;
    const float qy = pixel[warp_g * 3 + 1] + 24.0f;
    const float qz = ((pixel[warp_g * 3 + 2] - 425.0f) / 480.0f) * 128.0f;
    const int bx = (int)floorf(qx), by = (int)floorf(qy), bz = (int)floorf(qz);

    float acc = 0.0f;
#pragma unroll 8
    for (int k = 0; k < 64; k++) {
        const int ix = bx + (k >> 4) - 1;
        const int iy = by + ((k >> 2) & 3) - 1;
        const int iz = bz + (k & 3) - 1;
        const float sim = (float)ix * qx + (float)iy * qy + (float)iz * qz;
        acc += sim * __ldg(vol + (((ix * Wdim) + iy) * Ddim + iz) * 32 + lane);
    }
    float tot = acc;
#pragma unroll
    for (int o = 16; o; o >>= 1) tot += __shfl_xor_sync(0xffffffffu, tot, o);
    const float feat = acc / tot;

    float r0 = bq[lane], r1 = bq[lane + 32], r2 = bq[lane + 64], r3 = bq[lane + 96];
#pragma unroll 8
    for (int f = 0; f < 32; f++) {
        const float xf = __shfl_sync(0xffffffffu, feat, f);
        const float* wr = sWqT + f * 129 + lane;
        r0 += wr[0] * xf; r1 += wr[32] * xf; r2 += wr[64] * xf; r3 += wr[96] * xf;
    }
    float* bp = g_bias + (size_t)warp_g * LATD;
    bp[lane] = r0; bp[lane + 32] = r1; bp[lane + 64] = r2; bp[lane + 96] = r3;

    float s = fabsf(r0) + fabsf(r1) + fabsf(r2) + fabsf(r3);
#pragma unroll
    for (int o = 16; o; o >>= 1) s += __shfl_xor_sync(0xffffffffu, s, o);
    if (lane == 0) sred[tid >> 5] = s;
    __syncthreads();
    if (tid == 0) {
        float t = 0.0f;
        for (int i = 0; i < 8; i++) t += sred[i];
        g_partial[blockIdx.x] = t;
        __threadfence();
        slast = (atomicAdd(&g_done, 1) == GB - 1);
    }
    __syncthreads();
    if (slast) {
        float t = 0.0f;
        for (int i = tid; i < GB; i += 256) t += g_partial[i];
        __shared__ float sm2[256];
        sm2[tid] = t;
        __syncthreads();
        for (int o = 128; o; o >>= 1) {
            if (tid < o) sm2[tid] += sm2[tid + o];
            __syncthreads();
        }
        if (tid == 0) g_scale = ((float)NPTS * (float)LATD) / sm2[0];
    }
}

// ===== fused MLP: 4-warp CTA, 2 CTAs/SM, single W buffer, load-under-epilogue =====
#define SMEM_FUSED 65536

struct FParams {
    const float* world;
    const float* W0;
    const float* W9;
    const float* b[10];
    float* out;
};

__device__ __forceinline__ void prefetch_w(uint32_t sb, int s, int tid) {
    const int off = (s <= 8) ? (s - 1) * 8192 : ((s == 9) ? 65536 : 73728);
    const uint8_t* gh = (const uint8_t*)(g_wh + off);
    const uint8_t* gl = (const uint8_t*)(g_wl + off);
#pragma unroll
    for (int i = tid * 16; i < 32768; i += 128 * 16) {
        CPA(sb + i, gh + i);
        CPA(sb + 32768u + i, gl + i);
    }
}

__device__ __forceinline__ void mma_phase(
    uint32_t wbh, uint32_t wbl, int T,
    const uint32_t* ahi, const uint32_t* alo,
    float (*accm)[4], uint32_t (*accc)[2])
{
    const int t7 = T & 7;
    const int khalf = (T >> 3) & 1;
    const int nsel8 = ((T >> 4) & 1) * 8;
#pragma unroll
    for (int ks = 0; ks < 8; ks++) {
        const uint32_t kx = (uint32_t)(((2 * ks + khalf) ^ t7) << 4);
        const uint32_t rowb = (uint32_t)((nsel8 + t7) * 256) + kx;
#pragma unroll
        for (int nb = 0; nb < 16; nb += 2) {
            uint32_t bh[4], bl4[4];
            const uint32_t bo = rowb + (uint32_t)(nb * 2048);
            LDSM_X4(bh, wbh + bo);
            LDSM_X4(bl4, wbl + bo);
            MMAF(accm[nb],     ahi + 4 * ks, bh[0],  bh[1]);
            MMAF(accm[nb + 1], ahi + 4 * ks, bh[2],  bh[3]);
            MMAH(accc[nb],     ahi + 4 * ks, bl4[0], bl4[1]);
            MMAH(accc[nb + 1], ahi + 4 * ks, bl4[2], bl4[3]);
            MMAH(accc[nb],     alo + 4 * ks, bh[0],  bh[1]);
            MMAH(accc[nb + 1], alo + 4 * ks, bh[2],  bh[3]);
        }
    }
}

__global__ void __launch_bounds__(128, 2) k_fused(FParams p) {
    extern __shared__ uint8_t sm[];
    const int tid = threadIdx.x, w = tid >> 5, T = tid & 31;
    const int m0 = blockIdx.x * 64;
    const uint32_t sb = smem_u32(sm);
    const int mb = w * 16;
    const int c0 = (T & 3) * 2;
    const int rg1 = m0 + mb + (T >> 2), rg2 = rg1 + 8;

    prefetch_w(sb, 1, tid);
    CPA_COMMIT();

    uint32_t ahi[32], alo[32];
    float accm[16][4];
    uint32_t accc[16][2];

    // ---- layer 0 (3->128) * bias * scale -> softplus -> A fragments ----
    // (long FMA phase hides the W(1) cp.async)
    {
        const float sc = g_scale;
        const float* b0 = p.b[0];
        const float w1x = p.world[(size_t)rg1 * 3], w1y = p.world[(size_t)rg1 * 3 + 1],
                    w1z = p.world[(size_t)rg1 * 3 + 2];
        const float w2x = p.world[(size_t)rg2 * 3], w2y = p.world[(size_t)rg2 * 3 + 1],
                    w2z = p.world[(size_t)rg2 * 3 + 2];
#pragma unroll
        for (int nb = 0; nb < 16; nb++) {
            const int c = nb * 8 + c0;
            const float wa0 = p.W0[c * 3], wa1 = p.W0[c * 3 + 1], wa2 = p.W0[c * 3 + 2];
            const float wb0 = p.W0[c * 3 + 3], wb1 = p.W0[c * 3 + 4], wb2 = p.W0[c * 3 + 5];
            float y0 = b0[c]     + wa0 * w1x + wa1 * w1y + wa2 * w1z;
            float y1 = b0[c + 1] + wb0 * w1x + wb1 * w1y + wb2 * w1z;
            float y2 = b0[c]     + wa0 * w2x + wa1 * w2y + wa2 * w2z;
            float y3 = b0[c + 1] + wb0 * w2x + wb1 * w2y + wb2 * w2z;
            y0 *= g_bias[(size_t)rg1 * LATD + c] * sc;
            y1 *= g_bias[(size_t)rg1 * LATD + c + 1] * sc;
            y2 *= g_bias[(size_t)rg2 * LATD + c] * sc;
            y3 *= g_bias[(size_t)rg2 * LATD + c + 1] * sc;
            const int i0 = (nb >> 1) * 4 + (nb & 1) * 2;
            splith(sp100(y0), sp100(y1), ahi[i0], alo[i0]);
            splith(sp100(y2), sp100(y3), ahi[i0 + 1], alo[i0 + 1]);
        }
    }
    CPA_WAIT0();
    __syncthreads();   // W(1) visible to all warps

    const uint32_t wbh = sb, wbl = sb + 32768u;

    for (int s = 1; s <= 10; s++) {
#pragma unroll
        for (int i = 0; i < 16; i++) {
#pragma unroll
            for (int j = 0; j < 4; j++) accm[i][j] = 0.f;
            accc[i][0] = 0u; accc[i][1] = 0u;
        }
        mma_phase(wbh, wbl, T, ahi, alo, accm, accc);

        __syncthreads();   // all warps done reading W(s): buffer free for overwrite
        if (s < 10) { prefetch_w(sb, s + 1, tid); CPA_COMMIT(); }

        // ---- epilogue: registers only (overlaps the W(s+1) cp.async) ----
        if (s <= 8) {
            const float* bs = p.b[s];
            const bool skl = (s == 4);
            float wv1x = 0.f, wv1y = 0.f, wv1z = 0.f, wv2x = 0.f, wv2y = 0.f, wv2z = 0.f;
            if (skl) {
                wv1x = p.world[(size_t)rg1 * 3]; wv1y = p.world[(size_t)rg1 * 3 + 1];
                wv1z = p.world[(size_t)rg1 * 3 + 2];
                wv2x = p.world[(size_t)rg2 * 3]; wv2y = p.world[(size_t)rg2 * 3 + 1];
                wv2z = p.world[(size_t)rg2 * 3 + 2];
            }
#pragma unroll
            for (int nb = 0; nb < 16; nb++) {
                const int c = nb * 8 + c0;
                const float bv0 = bs[c], bv1 = bs[c + 1];
                const __half2 h1 = *reinterpret_cast<__half2*>(&accc[nb][0]);
                const __half2 h2 = *reinterpret_cast<__half2*>(&accc[nb][1]);
                float y0 = accm[nb][0] + __low2float(h1) + bv0;
                float y1 = accm[nb][1] + __high2float(h1) + bv1;
                float y2 = accm[nb][2] + __low2float(h2) + bv0;
                float y3 = accm[nb][3] + __high2float(h2) + bv1;
                if (skl && c >= 125) {
                    y0 = (c == 125) ? wv1x : ((c == 126) ? wv1y : wv1z);
                    y2 = (c == 125) ? wv2x : ((c == 126) ? wv2y : wv2z);
                }
                if (skl && c + 1 >= 125) {
                    y1 = (c + 1 == 125) ? wv1x : ((c + 1 == 126) ? wv1y : wv1z);
                    y3 = (c + 1 == 125) ? wv2x : ((c + 1 == 126) ? wv2y : wv2z);
                }
                const int i0 = (nb >> 1) * 4 + (nb & 1) * 2;
                splith(sp100(y0), sp100(y1), ahi[i0], alo[i0]);
                splith(sp100(y2), sp100(y3), ahi[i0 + 1], alo[i0 + 1]);
            }
        } else {
            const float* b9 = p.b[9];
            const int base = (s == 9) ? 0 : 128;
            float* o1 = p.out + (size_t)rg1 * OUTD + base;
            float* o2 = p.out + (size_t)rg2 * OUTD + base;
#pragma unroll
            for (int nb = 0; nb < 16; nb++) {
                const int c = nb * 8 + c0;
                const __half2 h1 = *reinterpret_cast<__half2*>(&accc[nb][0]);
                const __half2 h2 = *reinterpret_cast<__half2*>(&accc[nb][1]);
                o1[c]     = accm[nb][0] + __low2float(h1) + b9[base + c];
                o1[c + 1] = accm[nb][1] + __high2float(h1) + b9[base + c + 1];
                o2[c]     = accm[nb][2] + __low2float(h2) + b9[base + c];
                o2[c + 1] = accm[nb][3] + __high2float(h2) + b9[base + c + 1];
            }
            if (s == 10) {
                const float* w9c = p.W9 + 256 * 128;
                float s1 = 0.f, s2 = 0.f;
#pragma unroll
                for (int ks = 0; ks < 8; ks++) {
                    const int k0 = ks * 16 + c0;
                    const float wk0 = w9c[k0], wk1 = w9c[k0 + 1];
                    const float wk8 = w9c[k0 + 8], wk9 = w9c[k0 + 9];
                    float2 xa = upkh(ahi[4 * ks],     alo[4 * ks]);
                    float2 xb = upkh(ahi[4 * ks + 1], alo[4 * ks + 1]);
                    float2 xc = upkh(ahi[4 * ks + 2], alo[4 * ks + 2]);
                    float2 xd = upkh(ahi[4 * ks + 3], alo[4 * ks + 3]);
                    s1 += xa.x * wk0 + xa.y * wk1 + xc.x * wk8 + xc.y * wk9;
                    s2 += xb.x * wk0 + xb.y * wk1 + xd.x * wk8 + xd.y * wk9;
                }
                s1 += __shfl_xor_sync(0xffffffffu, s1, 1);
                s1 += __shfl_xor_sync(0xffffffffu, s1, 2);
                s2 += __shfl_xor_sync(0xffffffffu, s2, 1);
                s2 += __shfl_xor_sync(0xffffffffu, s2, 2);
                if ((T & 3) == 0) {
                    p.out[(size_t)rg1 * OUTD + 256] = s1 + b9[256];
                    p.out[(size_t)rg2 * OUTD + 256] = s2 + b9[256];
                }
            }
        }

        if (s < 10) {
            CPA_WAIT0();
            __syncthreads();   // W(s+1) loaded + visible
        }
    }
}

// ======================================================================
extern "C" void kernel_launch(void* const* d_in, const int* in_sizes, int n_in,
                              void* d_out, int out_size)
{
    const float* world = (const float*)d_in[0];
    const float* pixel = (const float*)d_in[1];
    const float* vol   = (const float*)d_in[2];
    const float* Wq    = (const float*)d_in[3];
    const float* bq    = (const float*)d_in[4];
    const float* Wl[10];
    const float* bl[10];
    for (int l = 0; l < 10; l++) {
        Wl[l] = (const float*)d_in[5 + 2 * l];
        bl[l] = (const float*)d_in[6 + 2 * l];
    }

    cudaFuncSetAttribute(k_fused, cudaFuncAttributeMaxDynamicSharedMemorySize, SMEM_FUSED);

    PW wp;
    for (int l = 0; l < 8; l++) wp.mid[l] = Wl[l + 1];
    wp.last = Wl[9];
    k_prep<<<320, 256>>>(wp);                    // idx 0

    k_gather<<<GB, 256>>>(pixel, vol, Wq, bq);   // idx 1

    k_nop<<<1, 32>>>();                          // idx 2

    FParams fp;
    fp.world = world;
    fp.W0 = Wl[0];
    fp.W9 = Wl[9];
    for (int l = 0; l < 10; l++) fp.b[l] = bl[l];
    fp.out = (float*)d_out;
    k_fused<<<NPTS / 64, 128, SMEM_FUSED>>>(fp);    // idx 3 <- ncu capture

    k_nop<<<1, 32>>>();                          // idx 4
}